// round 16
// baseline (speedup 1.0000x reference)
#include <cuda_runtime.h>
#include <cuda_fp16.h>
#include <cstdint>
#include <math.h>

#define B_  8
#define S_  1024
#define D_  768
#define H_  12
#define DH_ 64
#define FF_ 3072
#define E_  8
#define CAP_ 2048
#define T_  8192

// ---------------- scratch (device globals) ----------------------------------
__device__ float  g_tmp[T_*D_];
__device__ float  g_att[T_*D_];
__device__ float  g_ffn[T_*D_];
__device__ int    g_cnt[E_];
__device__ int    g_tokmap[E_*CAP_];
__device__ float  g_gate[T_];
// fp16 tensors
__device__ __half g_qh[B_*H_*S_*DH_];
__device__ __half g_kh[B_*H_*S_*DH_];
__device__ __half g_vh[B_*H_*S_*DH_];
__device__ __half g_xh[T_*D_];
__device__ __half g_wqh[D_*D_];
__device__ __half g_wkh[D_*D_];
__device__ __half g_wvh[D_*D_];
__device__ __half g_woh[D_*D_];
__device__ __half g_w1h[E_*D_*FF_];
__device__ __half g_w2h[E_*FF_*D_];
__device__ __half g_atth[T_*D_];
__device__ __half g_ctxh[T_*D_];
__device__ __half g_hh[50331648];          // E*CAP*FF fp16

__device__ __forceinline__ float gelu_f(float x) {
    return 0.5f * x * (1.0f + erff(x * 0.70710678118654752f));
}

__device__ __forceinline__ void cpa16(uint32_t dst, const void* src) {
    asm volatile("cp.async.ca.shared.global [%0], [%1], 16;" :: "r"(dst), "l"(src));
}
__device__ __forceinline__ void cpa_commit() {
    asm volatile("cp.async.commit_group;" ::: "memory");
}
__device__ __forceinline__ void cpa_wait0() {
    asm volatile("cp.async.wait_group 0;" ::: "memory");
}
__device__ __forceinline__ void mma16(float* c, const uint32_t* a, const uint32_t* b) {
    asm volatile(
        "mma.sync.aligned.m16n8k16.row.col.f32.f16.f16.f32 "
        "{%0,%1,%2,%3}, {%4,%5,%6,%7}, {%8,%9}, {%0,%1,%2,%3};\n"
        : "+f"(c[0]), "+f"(c[1]), "+f"(c[2]), "+f"(c[3])
        : "r"(a[0]), "r"(a[1]), "r"(a[2]), "r"(a[3]), "r"(b[0]), "r"(b[1]));
}
__device__ __forceinline__ void ldsm4(uint32_t* r, uint32_t addr) {
    asm volatile("ldmatrix.sync.aligned.m8n8.x4.b16 {%0,%1,%2,%3}, [%4];"
                 : "=r"(r[0]), "=r"(r[1]), "=r"(r[2]), "=r"(r[3]) : "r"(addr));
}
__device__ __forceinline__ void ldsm4t(uint32_t* r, uint32_t addr) {
    asm volatile("ldmatrix.sync.aligned.m8n8.x4.trans.shared.b16 {%0,%1,%2,%3}, [%4];"
                 : "=r"(r[0]), "=r"(r[1]), "=r"(r[2]), "=r"(r[3]) : "r"(addr));
}

// ---------------- fp32 -> fp16 conversions ------------------------------------
__global__ void f2h2(const float* __restrict__ s0, __half* __restrict__ d0,
                     const float* __restrict__ s1, __half* __restrict__ d1, int n4each) {
    int i = blockIdx.x * blockDim.x + threadIdx.x;
    const float* s; __half* d; int j;
    if (i < n4each)          { s = s0; d = d0; j = i; }
    else if (i < 2*n4each)   { s = s1; d = d1; j = i - n4each; }
    else return;
    float4 v = ((const float4*)s)[j];
    ((__half2*)d)[j*2]   = __floats2half2_rn(v.x, v.y);
    ((__half2*)d)[j*2+1] = __floats2half2_rn(v.z, v.w);
}
__global__ void f2h5(const float* __restrict__ x,  __half* dx,
                     const float* __restrict__ w0, __half* d0,
                     const float* __restrict__ w1, __half* d1,
                     const float* __restrict__ w2, __half* d2,
                     const float* __restrict__ w3, __half* d3) {
    constexpr int N4X = T_*D_/4, N4W = D_*D_/4;
    int i = blockIdx.x * blockDim.x + threadIdx.x;
    const float* s; __half* d; int j;
    if (i < N4X)            { s = x;  d = dx; j = i; }
    else if (i < N4X+N4W)   { s = w0; d = d0; j = i - N4X; }
    else if (i < N4X+2*N4W) { s = w1; d = d1; j = i - N4X - N4W; }
    else if (i < N4X+3*N4W) { s = w2; d = d2; j = i - N4X - 2*N4W; }
    else if (i < N4X+4*N4W) { s = w3; d = d3; j = i - N4X - 3*N4W; }
    else return;
    float4 v = ((const float4*)s)[j];
    ((__half2*)d)[j*2]   = __floats2half2_rn(v.x, v.y);
    ((__half2*)d)[j*2+1] = __floats2half2_rn(v.z, v.w);
}

// ================= fused flash attention (fp16 MMA, log2-domain softmax) =====
__global__ __launch_bounds__(256) void fattn(const float* __restrict__ mask)
{
    constexpr int LDK_H = 72, LDV_H = 72;
    constexpr int KBYTES = 64 * LDK_H * 2;
    constexpr int VBYTES = 64 * LDV_H * 2;
    constexpr int MBYTES = 256;
    constexpr int STAGE  = KBYTES + VBYTES + MBYTES;
    constexpr float LOG2E = 1.44269504088896f;
    extern __shared__ char smc[];

    const int tid = threadIdx.x, wid = tid >> 5, lane = tid & 31;
    const int g = lane >> 2, t = lane & 3;
    const int z = blockIdx.y, mBase = blockIdx.x * 128;
    const int bq = z / H_, hh = z % H_;
    const int m0 = mBase + wid * 16;

    const __half* Qp = g_qh + (size_t)z * S_ * DH_;
    const __half* Kp = g_kh + (size_t)z * S_ * DH_;
    const __half* Vp = g_vh + (size_t)z * S_ * DH_;

    const __half2 sc8 = __half2half2(__float2half(0.125f * LOG2E));
    uint32_t qf[4][4];
    #pragma unroll
    for (int ks = 0; ks < 4; ks++) {
        __half2 h0 = __hmul2(*(const __half2*)&Qp[(m0 + g)     * DH_ + ks*16 + 2*t],     sc8);
        __half2 h1 = __hmul2(*(const __half2*)&Qp[(m0 + g + 8) * DH_ + ks*16 + 2*t],     sc8);
        __half2 h2 = __hmul2(*(const __half2*)&Qp[(m0 + g)     * DH_ + ks*16 + 2*t + 8], sc8);
        __half2 h3 = __hmul2(*(const __half2*)&Qp[(m0 + g + 8) * DH_ + ks*16 + 2*t + 8], sc8);
        qf[ks][0] = *(uint32_t*)&h0; qf[ks][1] = *(uint32_t*)&h1;
        qf[ks][2] = *(uint32_t*)&h2; qf[ks][3] = *(uint32_t*)&h3;
    }

    float oacc[8][4];
    #pragma unroll
    for (int nt = 0; nt < 8; nt++)
        #pragma unroll
        for (int q = 0; q < 4; q++) oacc[nt][q] = 0.f;
    float lacc[4] = {0.f, 0.f, 0.f, 0.f};
    float mrow0 = -1e30f, mrow1 = -1e30f;
    const uint32_t ONE2 = 0x3C003C00u;

    uint32_t sU = (uint32_t)__cvta_generic_to_shared(smc);
    const uint32_t lmRow = (lane & 15);
    const uint32_t lmHalf = (lane >> 4) << 4;
    const uint32_t kOff = lmRow * (LDK_H*2) + lmHalf;
    const uint32_t vOff = lmRow * (LDV_H*2) + lmHalf;

    auto issue = [&](int kt) {
        const int stg = kt & 1;
        const uint32_t base = sU + stg * STAGE;
        #pragma unroll
        for (int i = 0; i < 2; i++) {
            int idx = tid + i * 256;
            int row = idx >> 3, c4 = idx & 7;
            cpa16(base + row * (LDK_H*2) + c4 * 16,
                  Kp + (size_t)(kt*64 + row) * DH_ + c4 * 8);
        }
        #pragma unroll
        for (int i = 0; i < 2; i++) {
            int idx = tid + i * 256;
            int row = idx >> 3, c4 = idx & 7;
            cpa16(base + KBYTES + row * (LDV_H*2) + c4 * 16,
                  Vp + (size_t)(kt*64 + row) * DH_ + c4 * 8);
        }
        if (tid < 16)
            cpa16(base + KBYTES + VBYTES + tid * 16, mask + bq * S_ + kt*64 + tid * 4);
        cpa_commit();
    };

    issue(0);
    for (int kt = 0; kt < 16; kt++) {
        cpa_wait0();
        __syncthreads();
        if (kt + 1 < 16) issue(kt + 1);

        const int stg = kt & 1;
        const uint32_t kBase = sU + stg * STAGE;
        const uint32_t vBase = kBase + KBYTES;
        const float* mS = (const float*)(smc + stg * STAGE + KBYTES + VBYTES);

        float sacc[8][4];
        #pragma unroll
        for (int nt = 0; nt < 8; nt++)
            #pragma unroll
            for (int q = 0; q < 4; q++) sacc[nt][q] = 0.f;
        #pragma unroll
        for (int ks = 0; ks < 4; ks++) {
            #pragma unroll
            for (int p = 0; p < 4; p++) {
                uint32_t r[4];
                ldsm4(r, kBase + kOff + p * 16 * (LDK_H*2) + ks * 32);
                uint32_t b0[2] = { r[0], r[2] };
                uint32_t b1[2] = { r[1], r[3] };
                mma16(sacc[2*p],   qf[ks], b0);
                mma16(sacc[2*p+1], qf[ks], b1);
            }
        }

        float mx0 = -1e30f, mx1 = -1e30f;
        #pragma unroll
        for (int nt = 0; nt < 8; nt++) {
            float mk0 = mS[nt*8 + 2*t], mk1 = mS[nt*8 + 2*t + 1];
            sacc[nt][0] = fmaf(mk0, LOG2E, sacc[nt][0]);
            sacc[nt][1] = fmaf(mk1, LOG2E, sacc[nt][1]);
            sacc[nt][2] = fmaf(mk0, LOG2E, sacc[nt][2]);
            sacc[nt][3] = fmaf(mk1, LOG2E, sacc[nt][3]);
            mx0 = fmaxf(mx0, fmaxf(sacc[nt][0], sacc[nt][1]));
            mx1 = fmaxf(mx1, fmaxf(sacc[nt][2], sacc[nt][3]));
        }
        mx0 = fmaxf(mx0, __shfl_xor_sync(0xffffffffu, mx0, 1));
        mx0 = fmaxf(mx0, __shfl_xor_sync(0xffffffffu, mx0, 2));
        mx1 = fmaxf(mx1, __shfl_xor_sync(0xffffffffu, mx1, 1));
        mx1 = fmaxf(mx1, __shfl_xor_sync(0xffffffffu, mx1, 2));

        float mn0 = fmaxf(mrow0, mx0), mn1 = fmaxf(mrow1, mx1);
        float a0 = exp2f(mrow0 - mn0), a1 = exp2f(mrow1 - mn1);
        mrow0 = mn0; mrow1 = mn1;

        uint32_t pf0[8], pf1[8];
        #pragma unroll
        for (int nt = 0; nt < 8; nt++) {
            float p0 = exp2f(sacc[nt][0] - mn0);
            float p1 = exp2f(sacc[nt][1] - mn0);
            float p2 = exp2f(sacc[nt][2] - mn1);
            float p3 = exp2f(sacc[nt][3] - mn1);
            __half2 hA = __floats2half2_rn(p0, p1);
            __half2 hB = __floats2half2_rn(p2, p3);
            pf0[nt] = *(uint32_t*)&hA;
            pf1[nt] = *(uint32_t*)&hB;
        }

        #pragma unroll
        for (int nt = 0; nt < 8; nt++) {
            oacc[nt][0] *= a0; oacc[nt][1] *= a0;
            oacc[nt][2] *= a1; oacc[nt][3] *= a1;
        }
        lacc[0] *= a0; lacc[1] *= a0; lacc[2] *= a1; lacc[3] *= a1;

        #pragma unroll
        for (int ks = 0; ks < 4; ks++) {
            uint32_t a[4] = { pf0[2*ks], pf1[2*ks], pf0[2*ks+1], pf1[2*ks+1] };
            uint32_t bones[2] = { ONE2, ONE2 };
            mma16(lacc, a, bones);
            #pragma unroll
            for (int p = 0; p < 4; p++) {
                uint32_t r[4];
                ldsm4t(r, vBase + vOff + ks * 16 * (LDV_H*2) + p * 32);
                uint32_t b0[2] = { r[0], r[1] };
                uint32_t b1[2] = { r[2], r[3] };
                mma16(oacc[2*p],   a, b0);
                mma16(oacc[2*p+1], a, b1);
            }
        }
    }

    float inv0 = 1.0f / lacc[0], inv1 = 1.0f / lacc[2];
    int mr0 = m0 + g, mr1 = m0 + g + 8;
    #pragma unroll
    for (int nt = 0; nt < 8; nt++) {
        int col = hh * DH_ + nt*8 + 2*t;
        *(__half2*)(g_ctxh + ((size_t)(bq * S_ + mr0)) * D_ + col) =
            __floats2half2_rn(oacc[nt][0] * inv0, oacc[nt][1] * inv0);
        *(__half2*)(g_ctxh + ((size_t)(bq * S_ + mr1)) * D_ + col) =
            __floats2half2_rn(oacc[nt][2] * inv1, oacc[nt][3] * inv1);
    }
}

// ---------------- fp16 mma.sync GEMM: 128x128 tile, K-chunk 64, 3 CTAs/SM ----
template<int MODE, int KK, int LDBG>
__global__ __launch_bounds__(128, 3)
void tgemm(const __half* __restrict__ Ag, const __half* __restrict__ Bg,
           const __half* __restrict__ Bg2, const __half* __restrict__ Bg3,
           const float* __restrict__ bias, const float* __restrict__ bias2,
           const float* __restrict__ bias3)
{
    constexpr int BN     = 128;
    constexpr int NC     = KK / 64;
    constexpr int NT     = 8;
    constexpr int LDA_H  = 72;
    constexpr int LDB_H  = 136;
    constexpr int ABYTES = 128 * LDA_H * 2;
    constexpr int BBYTES = 64 * LDB_H * 2;
    constexpr int STAGE  = ABYTES + BBYTES;
    constexpr int CS     = BN + 4;
    constexpr int BF4    = BN / 4;

    extern __shared__ char smc[];
    __shared__ int rIdx[128];
    __shared__ int s_cnt;

    const int tid = threadIdx.x, wid = tid >> 5, lane = tid & 31;
    const int wr = wid >> 1, wc = wid & 1;
    const int g = lane >> 2, t = lane & 3;
    const int mBase = blockIdx.y * 128, nBase = blockIdx.x * BN, z = blockIdx.z;
    const int e = (MODE >= 4) ? (mBase >> 11) : 0;

    if (MODE == 4 || MODE == 5) {
        if (tid == 0) s_cnt = g_cnt[e];
        __syncthreads();
        if ((mBase & (CAP_-1)) >= s_cnt) return;
    }

    const __half* A; const __half* Bp; const float* biasp = bias;
    if      (MODE == 0) { A = Ag; Bp = (z==0)?Bg:((z==1)?Bg2:Bg3);
                          biasp = (z==0)?bias:((z==1)?bias2:bias3); }
    else if (MODE == 3) { A = g_ctxh;  Bp = Bg; }
    else if (MODE == 4) { A = g_atth;  Bp = Bg + (size_t)e * D_ * FF_; }
    else                { A = g_hh;    Bp = Bg + (size_t)e * FF_ * D_; }

    {
        int m = mBase + tid, r = m;
        if (MODE == 4) {
            int pos = m & (CAP_-1);
            r = (pos < s_cnt) ? g_tokmap[e*CAP_ + pos] : 0;
        }
        rIdx[tid] = r;
    }
    __syncthreads();

    uint32_t sU = (uint32_t)__cvta_generic_to_shared(smc);
    const uint32_t aOff = (uint32_t)((wr*64 + (lane & 15)) * (LDA_H*2)) + ((lane >> 4) << 4);
    const uint32_t bOff = (uint32_t)((lane & 15) * (LDB_H*2)) + ((lane >> 4) << 4);

    auto issue = [&](int cix) {
        const int stg = cix & 1;
        const int k0 = cix * 64;
        const uint32_t aB = sU + stg * STAGE;
        #pragma unroll
        for (int i = 0; i < 8; i++) {
            int idx = tid + i * 128;
            int row = idx >> 3, c4 = idx & 7;
            cpa16(aB + row * (LDA_H*2) + c4 * 16,
                  A + (size_t)rIdx[row] * KK + k0 + c4 * 8);
        }
        const uint32_t bB = aB + ABYTES;
        #pragma unroll
        for (int i = 0; i < 8; i++) {
            int idx = tid + i * 128;
            int row = idx >> 4, c4 = idx & 15;
            cpa16(bB + row * (LDB_H*2) + c4 * 16,
                  Bp + (size_t)(k0 + row) * LDBG + nBase + c4 * 8);
        }
        cpa_commit();
    };

    float acc[4][NT][4];
    #pragma unroll
    for (int i = 0; i < 4; i++)
        #pragma unroll
        for (int j = 0; j < NT; j++)
            #pragma unroll
            for (int q = 0; q < 4; q++) acc[i][j][q] = 0.f;

    issue(0);
    for (int c = 0; c < NC; c++) {
        cpa_wait0();
        __syncthreads();
        if (c + 1 < NC) issue(c + 1);

        const int stg = c & 1;
        const uint32_t aBase = sU + stg * STAGE + aOff;
        const uint32_t bBase = sU + stg * STAGE + ABYTES + bOff + wc * 128;
        #pragma unroll
        for (int ks = 0; ks < 4; ks++) {
            uint32_t a[4][4];
            #pragma unroll
            for (int mt = 0; mt < 4; mt++)
                ldsm4(a[mt], aBase + mt * 16 * (LDA_H*2) + ks * 32);
            uint32_t b[NT][2];
            #pragma unroll
            for (int p = 0; p < 4; p++) {
                uint32_t r[4];
                ldsm4t(r, bBase + ks * 16 * (LDB_H*2) + p * 32);
                b[2*p][0]   = r[0]; b[2*p][1]   = r[1];
                b[2*p+1][0] = r[2]; b[2*p+1][1] = r[3];
            }
            #pragma unroll
            for (int mt = 0; mt < 4; mt++)
                #pragma unroll
                for (int nt = 0; nt < NT; nt++)
                    mma16(acc[mt][nt], a[mt], b[nt]);
        }
    }
    __syncthreads();

    // ---------------- epilogue ----------------
    float* cSf = (float*)smc;
    #pragma unroll
    for (int mt = 0; mt < 4; mt++) {
        #pragma unroll
        for (int nt = 0; nt < NT; nt++) {
            int r = wr*64 + mt*16 + g;
            int n = wc*64 + nt*8 + 2*t;
            *(float2*)(cSf + r*CS + n)     = make_float2(acc[mt][nt][0], acc[mt][nt][1]);
            *(float2*)(cSf + (r+8)*CS + n) = make_float2(acc[mt][nt][2], acc[mt][nt][3]);
        }
    }
    __syncthreads();

    constexpr int IT = (128 * BF4) / 128;
    #pragma unroll
    for (int it = 0; it < IT; it++) {
        int idx = it * 128 + tid;
        int row = idx / BF4, q = idx % BF4;
        float4 v = *(const float4*)(cSf + row*CS + q*4);
        int m  = mBase + row;
        int n0 = nBase + q*4;

        if (MODE == 0) {
            v.x += biasp[n0]; v.y += biasp[n0+1]; v.z += biasp[n0+2]; v.w += biasp[n0+3];
            int b = m >> 10, srow = m & 1023, hh = n0 >> 6, dh = n0 & 63;
            __half* dst = (z == 0) ? g_qh : ((z == 1) ? g_kh : g_vh);
            __half* p = dst + (((size_t)(b*H_ + hh)) * S_ + srow) * DH_ + dh;
            *(__half2*)(p)     = __floats2half2_rn(v.x, v.y);
            *(__half2*)(p + 2) = __floats2half2_rn(v.z, v.w);
        } else if (MODE == 3) {
            *(float4*)(g_tmp + (size_t)m * D_ + n0) = v;
        } else if (MODE == 4) {
            int pos = m & (CAP_-1);
            if (pos < s_cnt) {
                const float4 bb = *(const float4*)(bias + (size_t)e*FF_ + n0);
                __half* dst = g_hh + (size_t)m * FF_ + n0;
                *(__half2*)(dst)     = __floats2half2_rn(gelu_f(v.x+bb.x), gelu_f(v.y+bb.y));
                *(__half2*)(dst + 2) = __floats2half2_rn(gelu_f(v.z+bb.z), gelu_f(v.w+bb.w));
            }
        } else {
            int pos = m & (CAP_-1);
            if (pos < s_cnt) {
                int tok = g_tokmap[e*CAP_ + pos];
                float gsc = g_gate[tok];
                const float4 bb = *(const float4*)(bias + (size_t)e*D_ + n0);
                *(float4*)(g_ffn + (size_t)tok * D_ + n0) =
                    make_float4((v.x+bb.x)*gsc, (v.y+bb.y)*gsc,
                                (v.z+bb.z)*gsc, (v.w+bb.w)*gsc);
            }
        }
    }
}

// ---------------- layernorm (optional fp16 mirror output) --------------------
__global__ __launch_bounds__(256) void ln_kernel(
        const float* __restrict__ a, const float* __restrict__ bsum,
        const float* __restrict__ bias,
        const float* __restrict__ g, const float* __restrict__ beta,
        float* __restrict__ out, __half* __restrict__ outh)
{
    __shared__ float red[256];
    const int t = blockIdx.x, tid = threadIdx.x;
    const float* ap = a    + (size_t)t * D_;
    const float* bp = bsum + (size_t)t * D_;
    float v[3]; float s = 0.f;
    #pragma unroll
    for (int j=0;j<3;j++) {
        int i = tid + j*256;
        float x = ap[i] + bp[i];
        if (bias) x += bias[i];
        v[j] = x; s += x;
    }
    red[tid]=s; __syncthreads();
    for (int st=128; st>0; st>>=1) { if (tid<st) red[tid]+=red[tid+st]; __syncthreads(); }
    float mu = red[0] * (1.0f/768.0f);
    __syncthreads();
    float q = 0.f;
    #pragma unroll
    for (int j=0;j<3;j++) { float d = v[j]-mu; q += d*d; }
    red[tid]=q; __syncthreads();
    for (int st=128; st>0; st>>=1) { if (tid<st) red[tid]+=red[tid+st]; __syncthreads(); }
    float inv = rsqrtf(red[0]*(1.0f/768.0f) + 1e-12f);
    #pragma unroll
    for (int j=0;j<3;j++) {
        int i = tid + j*256;
        float y = (v[j]-mu)*inv*g[i] + beta[i];
        out[(size_t)t*D_ + i] = y;
        if (outh) outh[(size_t)t*D_ + i] = __float2half_rn(y);
    }
}

// ---------------- router ------------------------------------------------------
__global__ __launch_bounds__(256) void router_kernel(
        const float* __restrict__ Wr, const float* __restrict__ br)
{
    int warp = (blockIdx.x * blockDim.x + threadIdx.x) >> 5;
    int lane = threadIdx.x & 31;
    if (warp >= T_) return;
    const float* xrow = g_att + (size_t)warp * D_;
    float acc[E_];
    #pragma unroll
    for (int e=0;e<E_;e++) acc[e]=0.f;
    for (int i = lane; i < D_; i += 32) {
        float x = xrow[i];
        const float* w = Wr + i*E_;
        #pragma unroll
        for (int e=0;e<E_;e++) acc[e] += x * w[e];
    }
    #pragma unroll
    for (int e=0;e<E_;e++)
        #pragma unroll
        for (int o=16;o>0;o>>=1)
            acc[e] += __shfl_xor_sync(0xffffffffu, acc[e], o);
    if (lane == 0) {
        float best = -1e30f; int be = 0;
        #pragma unroll
        for (int e=0;e<E_;e++) {
            float l = acc[e] + br[e];
            acc[e] = l;
            if (l > best) { best = l; be = e; }
        }
        float sm = 0.f;
        #pragma unroll
        for (int e=0;e<E_;e++) sm += expf(acc[e] - best);
        float gate = 1.0f / sm;
        int pos = atomicAdd(&g_cnt[be], 1);
        if (pos < CAP_) {
            g_tokmap[be*CAP_ + pos] = warp;
            g_gate[warp] = gate;
        }
    }
}

__global__ void zero_small() {
    if (threadIdx.x < E_) g_cnt[threadIdx.x] = 0;
}

// ---------------- launch ------------------------------------------------------
extern "C" void kernel_launch(void* const* d_in, const int* in_sizes, int n_in,
                              void* d_out, int out_size) {
    const float* x    = (const float*)d_in[0];
    const float* mask = (const float*)d_in[1];
    const float* Wq   = (const float*)d_in[2];
    const float* bq   = (const float*)d_in[3];
    const float* Wk   = (const float*)d_in[4];
    const float* bk   = (const float*)d_in[5];
    const float* Wv   = (const float*)d_in[6];
    const float* bv   = (const float*)d_in[7];
    const float* Wo   = (const float*)d_in[8];
    const float* bo   = (const float*)d_in[9];
    const float* ln1g = (const float*)d_in[10];
    const float* ln1b = (const float*)d_in[11];
    const float* Wr   = (const float*)d_in[12];
    const float* br   = (const float*)d_in[13];
    const float* W1   = (const float*)d_in[14];
    const float* b1   = (const float*)d_in[15];
    const float* W2   = (const float*)d_in[16];
    const float* b2   = (const float*)d_in[17];
    const float* ln2g = (const float*)d_in[18];
    const float* ln2b = (const float*)d_in[19];
    float* out = (float*)d_out;

    float *p_tmp, *p_att, *p_ffn;
    __half *p_xh, *p_wqh, *p_wkh, *p_wvh, *p_woh, *p_w1h, *p_w2h, *p_atth;
    cudaGetSymbolAddress((void**)&p_tmp, g_tmp);
    cudaGetSymbolAddress((void**)&p_att, g_att);
    cudaGetSymbolAddress((void**)&p_ffn, g_ffn);
    cudaGetSymbolAddress((void**)&p_xh,  g_xh);
    cudaGetSymbolAddress((void**)&p_wqh, g_wqh);
    cudaGetSymbolAddress((void**)&p_wkh, g_wkh);
    cudaGetSymbolAddress((void**)&p_wvh, g_wvh);
    cudaGetSymbolAddress((void**)&p_woh, g_woh);
    cudaGetSymbolAddress((void**)&p_w1h, g_w1h);
    cudaGetSymbolAddress((void**)&p_w2h, g_w2h);
    cudaGetSymbolAddress((void**)&p_atth, g_atth);

    constexpr int SH_G  = 2 * 35840;                 // 71680 (<= 228/3 KB)
    constexpr int SH_FA = 2 * 18688;                 // 37376
    cudaFuncSetAttribute((const void*)tgemm<0,768,768>,   cudaFuncAttributeMaxDynamicSharedMemorySize, SH_G);
    cudaFuncSetAttribute((const void*)tgemm<3,768,768>,   cudaFuncAttributeMaxDynamicSharedMemorySize, SH_G);
    cudaFuncSetAttribute((const void*)tgemm<4,768,3072>,  cudaFuncAttributeMaxDynamicSharedMemorySize, SH_G);
    cudaFuncSetAttribute((const void*)tgemm<5,3072,768>,  cudaFuncAttributeMaxDynamicSharedMemorySize, SH_G);
    cudaFuncSetAttribute((const void*)fattn, cudaFuncAttributeMaxDynamicSharedMemorySize, SH_FA);

    zero_small<<<1, 32>>>();

    // merged small fp32->fp16 conversions (x, Wq, Wk, Wv, Wo)
    constexpr int N4ALL = T_*D_/4 + 4*(D_*D_/4);
    f2h5<<<(N4ALL + 255)/256, 256>>>(x, p_xh, Wq, p_wqh, Wk, p_wkh, Wv, p_wvh, Wo, p_woh);

    // fused QKV projections (fp16 in, fp16 q/k/v out)
    tgemm<0,768,768><<<dim3(6,64,3), 128, SH_G>>>(p_xh, p_wqh, p_wkh, p_wvh, bq, bk, bv);

    // fused flash attention (fp16 MMA, register P, log2-domain softmax)
    fattn<<<dim3(8, 96), 256, SH_FA>>>(mask);

    // att = LN1(x + ctxh@Wo + bo) ; fp16 mirror for MoE
    tgemm<3,768,768><<<dim3(6,64,1), 128, SH_G>>>(nullptr, p_woh, nullptr, nullptr, nullptr, nullptr, nullptr);
    ln_kernel<<<T_, 256>>>(x, p_tmp, bo, ln1g, ln1b, p_att, p_atth);

    // router + MoE (fp16 operands, fp32 accum)
    router_kernel<<<T_/8, 256>>>(Wr, br);
    f2h2<<<(2*(E_*D_*FF_/4) + 255)/256, 256>>>(W1, p_w1h, W2, p_w2h, E_*D_*FF_/4);
    tgemm<4,768,3072><<<dim3(FF_/128, (E_*CAP_)/128, 1), 128, SH_G>>>(nullptr, p_w1h, nullptr, nullptr, b1, nullptr, nullptr);
    tgemm<5,3072,768><<<dim3(D_/128, (E_*CAP_)/128, 1), 128, SH_G>>>(nullptr, p_w2h, nullptr, nullptr, b2, nullptr, nullptr);

    // out = LN2(att + ffn)
    ln_kernel<<<T_, 256>>>(p_att, p_ffn, nullptr, ln2g, ln2b, out, nullptr);
}

// round 17
// speedup vs baseline: 1.0836x; 1.0836x over previous
#include <cuda_runtime.h>
#include <cuda_fp16.h>
#include <cstdint>
#include <math.h>

#define B_  8
#define S_  1024
#define D_  768
#define H_  12
#define DH_ 64
#define FF_ 3072
#define E_  8
#define CAP_ 2048
#define T_  8192

// ---------------- scratch (device globals) ----------------------------------
__device__ float  g_tmp[T_*D_];
__device__ float  g_att[T_*D_];
__device__ float  g_ffn[T_*D_];
__device__ int    g_cnt[E_];
__device__ int    g_tokmap[E_*CAP_];
__device__ float  g_gate[T_];
// fp16 tensors
__device__ __half g_qh[B_*H_*S_*DH_];
__device__ __half g_kh[B_*H_*S_*DH_];
__device__ __half g_vh[B_*H_*S_*DH_];
__device__ __half g_xh[T_*D_];
__device__ __half g_wqh[D_*D_];
__device__ __half g_wkh[D_*D_];
__device__ __half g_wvh[D_*D_];
__device__ __half g_woh[D_*D_];
__device__ __half g_w1h[E_*D_*FF_];
__device__ __half g_w2h[E_*FF_*D_];
__device__ __half g_atth[T_*D_];
__device__ __half g_ctxh[T_*D_];
__device__ __half g_hh[50331648];          // E*CAP*FF fp16

__device__ __forceinline__ float gelu_f(float x) {
    return 0.5f * x * (1.0f + erff(x * 0.70710678118654752f));
}

__device__ __forceinline__ void cpa16(uint32_t dst, const void* src) {
    asm volatile("cp.async.ca.shared.global [%0], [%1], 16;" :: "r"(dst), "l"(src));
}
__device__ __forceinline__ void cpa_commit() {
    asm volatile("cp.async.commit_group;" ::: "memory");
}
__device__ __forceinline__ void cpa_wait0() {
    asm volatile("cp.async.wait_group 0;" ::: "memory");
}
__device__ __forceinline__ void mma16(float* c, const uint32_t* a, const uint32_t* b) {
    asm volatile(
        "mma.sync.aligned.m16n8k16.row.col.f32.f16.f16.f32 "
        "{%0,%1,%2,%3}, {%4,%5,%6,%7}, {%8,%9}, {%0,%1,%2,%3};\n"
        : "+f"(c[0]), "+f"(c[1]), "+f"(c[2]), "+f"(c[3])
        : "r"(a[0]), "r"(a[1]), "r"(a[2]), "r"(a[3]), "r"(b[0]), "r"(b[1]));
}
__device__ __forceinline__ void ldsm4(uint32_t* r, uint32_t addr) {
    asm volatile("ldmatrix.sync.aligned.m8n8.x4.b16 {%0,%1,%2,%3}, [%4];"
                 : "=r"(r[0]), "=r"(r[1]), "=r"(r[2]), "=r"(r[3]) : "r"(addr));
}
__device__ __forceinline__ void ldsm4t(uint32_t* r, uint32_t addr) {
    asm volatile("ldmatrix.sync.aligned.m8n8.x4.trans.shared.b16 {%0,%1,%2,%3}, [%4];"
                 : "=r"(r[0]), "=r"(r[1]), "=r"(r[2]), "=r"(r[3]) : "r"(addr));
}

// ---------------- fp32 -> fp16 conversions ------------------------------------
__global__ void f2h2(const float* __restrict__ s0, __half* __restrict__ d0,
                     const float* __restrict__ s1, __half* __restrict__ d1, int n4each) {
    int i = blockIdx.x * blockDim.x + threadIdx.x;
    const float* s; __half* d; int j;
    if (i < n4each)          { s = s0; d = d0; j = i; }
    else if (i < 2*n4each)   { s = s1; d = d1; j = i - n4each; }
    else return;
    float4 v = ((const float4*)s)[j];
    ((__half2*)d)[j*2]   = __floats2half2_rn(v.x, v.y);
    ((__half2*)d)[j*2+1] = __floats2half2_rn(v.z, v.w);
}
__global__ void f2h5(const float* __restrict__ x,  __half* dx,
                     const float* __restrict__ w0, __half* d0,
                     const float* __restrict__ w1, __half* d1,
                     const float* __restrict__ w2, __half* d2,
                     const float* __restrict__ w3, __half* d3) {
    constexpr int N4X = T_*D_/4, N4W = D_*D_/4;
    int i = blockIdx.x * blockDim.x + threadIdx.x;
    const float* s; __half* d; int j;
    if (i < N4X)            { s = x;  d = dx; j = i; }
    else if (i < N4X+N4W)   { s = w0; d = d0; j = i - N4X; }
    else if (i < N4X+2*N4W) { s = w1; d = d1; j = i - N4X - N4W; }
    else if (i < N4X+3*N4W) { s = w2; d = d2; j = i - N4X - 2*N4W; }
    else if (i < N4X+4*N4W) { s = w3; d = d3; j = i - N4X - 3*N4W; }
    else return;
    float4 v = ((const float4*)s)[j];
    ((__half2*)d)[j*2]   = __floats2half2_rn(v.x, v.y);
    ((__half2*)d)[j*2+1] = __floats2half2_rn(v.z, v.w);
}

// ================= fused flash attention (fp16 MMA, log2-domain softmax) =====
__global__ __launch_bounds__(256) void fattn(const float* __restrict__ mask)
{
    constexpr int LDK_H = 72, LDV_H = 72;
    constexpr int KBYTES = 64 * LDK_H * 2;
    constexpr int VBYTES = 64 * LDV_H * 2;
    constexpr int MBYTES = 256;
    constexpr int STAGE  = KBYTES + VBYTES + MBYTES;
    constexpr float LOG2E = 1.44269504088896f;
    extern __shared__ char smc[];

    const int tid = threadIdx.x, wid = tid >> 5, lane = tid & 31;
    const int g = lane >> 2, t = lane & 3;
    const int z = blockIdx.y, mBase = blockIdx.x * 128;
    const int bq = z / H_, hh = z % H_;
    const int m0 = mBase + wid * 16;

    const __half* Qp = g_qh + (size_t)z * S_ * DH_;
    const __half* Kp = g_kh + (size_t)z * S_ * DH_;
    const __half* Vp = g_vh + (size_t)z * S_ * DH_;

    const __half2 sc8 = __half2half2(__float2half(0.125f * LOG2E));
    uint32_t qf[4][4];
    #pragma unroll
    for (int ks = 0; ks < 4; ks++) {
        __half2 h0 = __hmul2(*(const __half2*)&Qp[(m0 + g)     * DH_ + ks*16 + 2*t],     sc8);
        __half2 h1 = __hmul2(*(const __half2*)&Qp[(m0 + g + 8) * DH_ + ks*16 + 2*t],     sc8);
        __half2 h2 = __hmul2(*(const __half2*)&Qp[(m0 + g)     * DH_ + ks*16 + 2*t + 8], sc8);
        __half2 h3 = __hmul2(*(const __half2*)&Qp[(m0 + g + 8) * DH_ + ks*16 + 2*t + 8], sc8);
        qf[ks][0] = *(uint32_t*)&h0; qf[ks][1] = *(uint32_t*)&h1;
        qf[ks][2] = *(uint32_t*)&h2; qf[ks][3] = *(uint32_t*)&h3;
    }

    float oacc[8][4];
    #pragma unroll
    for (int nt = 0; nt < 8; nt++)
        #pragma unroll
        for (int q = 0; q < 4; q++) oacc[nt][q] = 0.f;
    float lacc[4] = {0.f, 0.f, 0.f, 0.f};
    float mrow0 = -1e30f, mrow1 = -1e30f;
    const uint32_t ONE2 = 0x3C003C00u;

    uint32_t sU = (uint32_t)__cvta_generic_to_shared(smc);
    const uint32_t lmRow = (lane & 15);
    const uint32_t lmHalf = (lane >> 4) << 4;
    const uint32_t kOff = lmRow * (LDK_H*2) + lmHalf;
    const uint32_t vOff = lmRow * (LDV_H*2) + lmHalf;

    auto issue = [&](int kt) {
        const int stg = kt & 1;
        const uint32_t base = sU + stg * STAGE;
        #pragma unroll
        for (int i = 0; i < 2; i++) {
            int idx = tid + i * 256;
            int row = idx >> 3, c4 = idx & 7;
            cpa16(base + row * (LDK_H*2) + c4 * 16,
                  Kp + (size_t)(kt*64 + row) * DH_ + c4 * 8);
        }
        #pragma unroll
        for (int i = 0; i < 2; i++) {
            int idx = tid + i * 256;
            int row = idx >> 3, c4 = idx & 7;
            cpa16(base + KBYTES + row * (LDV_H*2) + c4 * 16,
                  Vp + (size_t)(kt*64 + row) * DH_ + c4 * 8);
        }
        if (tid < 16)
            cpa16(base + KBYTES + VBYTES + tid * 16, mask + bq * S_ + kt*64 + tid * 4);
        cpa_commit();
    };

    issue(0);
    for (int kt = 0; kt < 16; kt++) {
        cpa_wait0();
        __syncthreads();
        if (kt + 1 < 16) issue(kt + 1);

        const int stg = kt & 1;
        const uint32_t kBase = sU + stg * STAGE;
        const uint32_t vBase = kBase + KBYTES;
        const float* mS = (const float*)(smc + stg * STAGE + KBYTES + VBYTES);

        float sacc[8][4];
        #pragma unroll
        for (int nt = 0; nt < 8; nt++)
            #pragma unroll
            for (int q = 0; q < 4; q++) sacc[nt][q] = 0.f;
        #pragma unroll
        for (int ks = 0; ks < 4; ks++) {
            #pragma unroll
            for (int p = 0; p < 4; p++) {
                uint32_t r[4];
                ldsm4(r, kBase + kOff + p * 16 * (LDK_H*2) + ks * 32);
                uint32_t b0[2] = { r[0], r[2] };
                uint32_t b1[2] = { r[1], r[3] };
                mma16(sacc[2*p],   qf[ks], b0);
                mma16(sacc[2*p+1], qf[ks], b1);
            }
        }

        float mx0 = -1e30f, mx1 = -1e30f;
        #pragma unroll
        for (int nt = 0; nt < 8; nt++) {
            float mk0 = mS[nt*8 + 2*t], mk1 = mS[nt*8 + 2*t + 1];
            sacc[nt][0] = fmaf(mk0, LOG2E, sacc[nt][0]);
            sacc[nt][1] = fmaf(mk1, LOG2E, sacc[nt][1]);
            sacc[nt][2] = fmaf(mk0, LOG2E, sacc[nt][2]);
            sacc[nt][3] = fmaf(mk1, LOG2E, sacc[nt][3]);
            mx0 = fmaxf(mx0, fmaxf(sacc[nt][0], sacc[nt][1]));
            mx1 = fmaxf(mx1, fmaxf(sacc[nt][2], sacc[nt][3]));
        }
        mx0 = fmaxf(mx0, __shfl_xor_sync(0xffffffffu, mx0, 1));
        mx0 = fmaxf(mx0, __shfl_xor_sync(0xffffffffu, mx0, 2));
        mx1 = fmaxf(mx1, __shfl_xor_sync(0xffffffffu, mx1, 1));
        mx1 = fmaxf(mx1, __shfl_xor_sync(0xffffffffu, mx1, 2));

        float mn0 = fmaxf(mrow0, mx0), mn1 = fmaxf(mrow1, mx1);
        float a0 = exp2f(mrow0 - mn0), a1 = exp2f(mrow1 - mn1);
        mrow0 = mn0; mrow1 = mn1;

        uint32_t pf0[8], pf1[8];
        #pragma unroll
        for (int nt = 0; nt < 8; nt++) {
            float p0 = exp2f(sacc[nt][0] - mn0);
            float p1 = exp2f(sacc[nt][1] - mn0);
            float p2 = exp2f(sacc[nt][2] - mn1);
            float p3 = exp2f(sacc[nt][3] - mn1);
            __half2 hA = __floats2half2_rn(p0, p1);
            __half2 hB = __floats2half2_rn(p2, p3);
            pf0[nt] = *(uint32_t*)&hA;
            pf1[nt] = *(uint32_t*)&hB;
        }

        #pragma unroll
        for (int nt = 0; nt < 8; nt++) {
            oacc[nt][0] *= a0; oacc[nt][1] *= a0;
            oacc[nt][2] *= a1; oacc[nt][3] *= a1;
        }
        lacc[0] *= a0; lacc[1] *= a0; lacc[2] *= a1; lacc[3] *= a1;

        #pragma unroll
        for (int ks = 0; ks < 4; ks++) {
            uint32_t a[4] = { pf0[2*ks], pf1[2*ks], pf0[2*ks+1], pf1[2*ks+1] };
            uint32_t bones[2] = { ONE2, ONE2 };
            mma16(lacc, a, bones);
            #pragma unroll
            for (int p = 0; p < 4; p++) {
                uint32_t r[4];
                ldsm4t(r, vBase + vOff + ks * 16 * (LDV_H*2) + p * 32);
                uint32_t b0[2] = { r[0], r[1] };
                uint32_t b1[2] = { r[2], r[3] };
                mma16(oacc[2*p],   a, b0);
                mma16(oacc[2*p+1], a, b1);
            }
        }
    }

    float inv0 = 1.0f / lacc[0], inv1 = 1.0f / lacc[2];
    int mr0 = m0 + g, mr1 = m0 + g + 8;
    #pragma unroll
    for (int nt = 0; nt < 8; nt++) {
        int col = hh * DH_ + nt*8 + 2*t;
        *(__half2*)(g_ctxh + ((size_t)(bq * S_ + mr0)) * D_ + col) =
            __floats2half2_rn(oacc[nt][0] * inv0, oacc[nt][1] * inv0);
        *(__half2*)(g_ctxh + ((size_t)(bq * S_ + mr1)) * D_ + col) =
            __floats2half2_rn(oacc[nt][2] * inv1, oacc[nt][3] * inv1);
    }
}

// ---------------- fp16 mma.sync GEMM: 128x128 tile, K-chunk 64, 2 CTAs/SM ----
template<int MODE, int KK, int LDBG>
__global__ __launch_bounds__(128, 2)
void tgemm(const __half* __restrict__ Ag, const __half* __restrict__ Bg,
           const __half* __restrict__ Bg2, const __half* __restrict__ Bg3,
           const float* __restrict__ bias, const float* __restrict__ bias2,
           const float* __restrict__ bias3)
{
    constexpr int BN     = 128;
    constexpr int NC     = KK / 64;
    constexpr int NT     = 8;
    constexpr int LDA_H  = 72;
    constexpr int LDB_H  = 136;
    constexpr int ABYTES = 128 * LDA_H * 2;
    constexpr int BBYTES = 64 * LDB_H * 2;
    constexpr int STAGE  = ABYTES + BBYTES;
    constexpr int CS     = BN + 4;
    constexpr int BF4    = BN / 4;

    extern __shared__ char smc[];
    __shared__ int rIdx[128];
    __shared__ int s_cnt;

    const int tid = threadIdx.x, wid = tid >> 5, lane = tid & 31;
    const int wr = wid >> 1, wc = wid & 1;
    const int g = lane >> 2, t = lane & 3;
    const int mBase = blockIdx.y * 128, nBase = blockIdx.x * BN, z = blockIdx.z;
    const int e = (MODE >= 4) ? (mBase >> 11) : 0;

    if (MODE == 4 || MODE == 5) {
        if (tid == 0) s_cnt = g_cnt[e];
        __syncthreads();
        if ((mBase & (CAP_-1)) >= s_cnt) return;
    }

    const __half* A; const __half* Bp; const float* biasp = bias;
    if      (MODE == 0) { A = Ag; Bp = (z==0)?Bg:((z==1)?Bg2:Bg3);
                          biasp = (z==0)?bias:((z==1)?bias2:bias3); }
    else if (MODE == 3) { A = g_ctxh;  Bp = Bg; }
    else if (MODE == 4) { A = g_atth;  Bp = Bg + (size_t)e * D_ * FF_; }
    else                { A = g_hh;    Bp = Bg + (size_t)e * FF_ * D_; }

    if (MODE == 4) {
        int m = mBase + tid;
        int pos = m & (CAP_-1);
        rIdx[tid] = (pos < s_cnt) ? g_tokmap[e*CAP_ + pos] : 0;
        __syncthreads();
    }

    uint32_t sU = (uint32_t)__cvta_generic_to_shared(smc);
    const uint32_t aOff = (uint32_t)((wr*64 + (lane & 15)) * (LDA_H*2)) + ((lane >> 4) << 4);
    const uint32_t bOff = (uint32_t)((lane & 15) * (LDB_H*2)) + ((lane >> 4) << 4);

    auto issue = [&](int cix) {
        const int stg = cix & 1;
        const int k0 = cix * 64;
        const uint32_t aB = sU + stg * STAGE;
        #pragma unroll
        for (int i = 0; i < 8; i++) {
            int idx = tid + i * 128;
            int row = idx >> 3, c4 = idx & 7;
            int r = (MODE == 4) ? rIdx[row] : (mBase + row);
            cpa16(aB + row * (LDA_H*2) + c4 * 16,
                  A + (size_t)r * KK + k0 + c4 * 8);
        }
        const uint32_t bB = aB + ABYTES;
        #pragma unroll
        for (int i = 0; i < 8; i++) {
            int idx = tid + i * 128;
            int row = idx >> 4, c4 = idx & 15;
            cpa16(bB + row * (LDB_H*2) + c4 * 16,
                  Bp + (size_t)(k0 + row) * LDBG + nBase + c4 * 8);
        }
        cpa_commit();
    };

    float acc[4][NT][4];
    #pragma unroll
    for (int i = 0; i < 4; i++)
        #pragma unroll
        for (int j = 0; j < NT; j++)
            #pragma unroll
            for (int q = 0; q < 4; q++) acc[i][j][q] = 0.f;

    issue(0);
    for (int c = 0; c < NC; c++) {
        cpa_wait0();
        __syncthreads();
        if (c + 1 < NC) issue(c + 1);

        const int stg = c & 1;
        const uint32_t aBase = sU + stg * STAGE + aOff;
        const uint32_t bBase = sU + stg * STAGE + ABYTES + bOff + wc * 128;
        #pragma unroll
        for (int ks = 0; ks < 4; ks++) {
            uint32_t a[4][4];
            #pragma unroll
            for (int mt = 0; mt < 4; mt++)
                ldsm4(a[mt], aBase + mt * 16 * (LDA_H*2) + ks * 32);
            uint32_t b[NT][2];
            #pragma unroll
            for (int p = 0; p < 4; p++) {
                uint32_t r[4];
                ldsm4t(r, bBase + ks * 16 * (LDB_H*2) + p * 32);
                b[2*p][0]   = r[0]; b[2*p][1]   = r[1];
                b[2*p+1][0] = r[2]; b[2*p+1][1] = r[3];
            }
            #pragma unroll
            for (int mt = 0; mt < 4; mt++)
                #pragma unroll
                for (int nt = 0; nt < NT; nt++)
                    mma16(acc[mt][nt], a[mt], b[nt]);
        }
    }
    __syncthreads();

    // ---------------- epilogue ----------------
    float* cSf = (float*)smc;
    #pragma unroll
    for (int mt = 0; mt < 4; mt++) {
        #pragma unroll
        for (int nt = 0; nt < NT; nt++) {
            int r = wr*64 + mt*16 + g;
            int n = wc*64 + nt*8 + 2*t;
            *(float2*)(cSf + r*CS + n)     = make_float2(acc[mt][nt][0], acc[mt][nt][1]);
            *(float2*)(cSf + (r+8)*CS + n) = make_float2(acc[mt][nt][2], acc[mt][nt][3]);
        }
    }
    __syncthreads();

    constexpr int IT = (128 * BF4) / 128;
    #pragma unroll
    for (int it = 0; it < IT; it++) {
        int idx = it * 128 + tid;
        int row = idx / BF4, q = idx % BF4;
        float4 v = *(const float4*)(cSf + row*CS + q*4);
        int m  = mBase + row;
        int n0 = nBase + q*4;

        if (MODE == 0) {
            v.x += biasp[n0]; v.y += biasp[n0+1]; v.z += biasp[n0+2]; v.w += biasp[n0+3];
            int b = m >> 10, srow = m & 1023, hh = n0 >> 6, dh = n0 & 63;
            __half* dst = (z == 0) ? g_qh : ((z == 1) ? g_kh : g_vh);
            __half* p = dst + (((size_t)(b*H_ + hh)) * S_ + srow) * DH_ + dh;
            *(__half2*)(p)     = __floats2half2_rn(v.x, v.y);
            *(__half2*)(p + 2) = __floats2half2_rn(v.z, v.w);
        } else if (MODE == 3) {
            *(float4*)(g_tmp + (size_t)m * D_ + n0) = v;
        } else if (MODE == 4) {
            int pos = m & (CAP_-1);
            if (pos < s_cnt) {
                const float4 bb = *(const float4*)(bias + (size_t)e*FF_ + n0);
                __half* dst = g_hh + (size_t)m * FF_ + n0;
                *(__half2*)(dst)     = __floats2half2_rn(gelu_f(v.x+bb.x), gelu_f(v.y+bb.y));
                *(__half2*)(dst + 2) = __floats2half2_rn(gelu_f(v.z+bb.z), gelu_f(v.w+bb.w));
            }
        } else {
            int pos = m & (CAP_-1);
            if (pos < s_cnt) {
                int tok = g_tokmap[e*CAP_ + pos];
                float gsc = g_gate[tok];
                const float4 bb = *(const float4*)(bias + (size_t)e*D_ + n0);
                *(float4*)(g_ffn + (size_t)tok * D_ + n0) =
                    make_float4((v.x+bb.x)*gsc, (v.y+bb.y)*gsc,
                                (v.z+bb.z)*gsc, (v.w+bb.w)*gsc);
            }
        }
    }
}

// ---------------- layernorm (optional fp16 mirror output) --------------------
__global__ __launch_bounds__(256) void ln_kernel(
        const float* __restrict__ a, const float* __restrict__ bsum,
        const float* __restrict__ bias,
        const float* __restrict__ g, const float* __restrict__ beta,
        float* __restrict__ out, __half* __restrict__ outh)
{
    __shared__ float red[256];
    const int t = blockIdx.x, tid = threadIdx.x;
    const float* ap = a    + (size_t)t * D_;
    const float* bp = bsum + (size_t)t * D_;
    float v[3]; float s = 0.f;
    #pragma unroll
    for (int j=0;j<3;j++) {
        int i = tid + j*256;
        float x = ap[i] + bp[i];
        if (bias) x += bias[i];
        v[j] = x; s += x;
    }
    red[tid]=s; __syncthreads();
    for (int st=128; st>0; st>>=1) { if (tid<st) red[tid]+=red[tid+st]; __syncthreads(); }
    float mu = red[0] * (1.0f/768.0f);
    __syncthreads();
    float q = 0.f;
    #pragma unroll
    for (int j=0;j<3;j++) { float d = v[j]-mu; q += d*d; }
    red[tid]=q; __syncthreads();
    for (int st=128; st>0; st>>=1) { if (tid<st) red[tid]+=red[tid+st]; __syncthreads(); }
    float inv = rsqrtf(red[0]*(1.0f/768.0f) + 1e-12f);
    #pragma unroll
    for (int j=0;j<3;j++) {
        int i = tid + j*256;
        float y = (v[j]-mu)*inv*g[i] + beta[i];
        out[(size_t)t*D_ + i] = y;
        if (outh) outh[(size_t)t*D_ + i] = __float2half_rn(y);
    }
}

// ---------------- router ------------------------------------------------------
__global__ __launch_bounds__(256) void router_kernel(
        const float* __restrict__ Wr, const float* __restrict__ br)
{
    int warp = (blockIdx.x * blockDim.x + threadIdx.x) >> 5;
    int lane = threadIdx.x & 31;
    if (warp >= T_) return;
    const float* xrow = g_att + (size_t)warp * D_;
    float acc[E_];
    #pragma unroll
    for (int e=0;e<E_;e++) acc[e]=0.f;
    for (int i = lane; i < D_; i += 32) {
        float x = xrow[i];
        const float* w = Wr + i*E_;
        #pragma unroll
        for (int e=0;e<E_;e++) acc[e] += x * w[e];
    }
    #pragma unroll
    for (int e=0;e<E_;e++)
        #pragma unroll
        for (int o=16;o>0;o>>=1)
            acc[e] += __shfl_xor_sync(0xffffffffu, acc[e], o);
    if (lane == 0) {
        float best = -1e30f; int be = 0;
        #pragma unroll
        for (int e=0;e<E_;e++) {
            float l = acc[e] + br[e];
            acc[e] = l;
            if (l > best) { best = l; be = e; }
        }
        float sm = 0.f;
        #pragma unroll
        for (int e=0;e<E_;e++) sm += expf(acc[e] - best);
        float gate = 1.0f / sm;
        int pos = atomicAdd(&g_cnt[be], 1);
        if (pos < CAP_) {
            g_tokmap[be*CAP_ + pos] = warp;
            g_gate[warp] = gate;
        }
    }
}

__global__ void zero_small() {
    if (threadIdx.x < E_) g_cnt[threadIdx.x] = 0;
}

// ---------------- launch ------------------------------------------------------
extern "C" void kernel_launch(void* const* d_in, const int* in_sizes, int n_in,
                              void* d_out, int out_size) {
    const float* x    = (const float*)d_in[0];
    const float* mask = (const float*)d_in[1];
    const float* Wq   = (const float*)d_in[2];
    const float* bq   = (const float*)d_in[3];
    const float* Wk   = (const float*)d_in[4];
    const float* bk   = (const float*)d_in[5];
    const float* Wv   = (const float*)d_in[6];
    const float* bv   = (const float*)d_in[7];
    const float* Wo   = (const float*)d_in[8];
    const float* bo   = (const float*)d_in[9];
    const float* ln1g = (const float*)d_in[10];
    const float* ln1b = (const float*)d_in[11];
    const float* Wr   = (const float*)d_in[12];
    const float* br   = (const float*)d_in[13];
    const float* W1   = (const float*)d_in[14];
    const float* b1   = (const float*)d_in[15];
    const float* W2   = (const float*)d_in[16];
    const float* b2   = (const float*)d_in[17];
    const float* ln2g = (const float*)d_in[18];
    const float* ln2b = (const float*)d_in[19];
    float* out = (float*)d_out;

    float *p_tmp, *p_att, *p_ffn;
    __half *p_xh, *p_wqh, *p_wkh, *p_wvh, *p_woh, *p_w1h, *p_w2h, *p_atth;
    cudaGetSymbolAddress((void**)&p_tmp, g_tmp);
    cudaGetSymbolAddress((void**)&p_att, g_att);
    cudaGetSymbolAddress((void**)&p_ffn, g_ffn);
    cudaGetSymbolAddress((void**)&p_xh,  g_xh);
    cudaGetSymbolAddress((void**)&p_wqh, g_wqh);
    cudaGetSymbolAddress((void**)&p_wkh, g_wkh);
    cudaGetSymbolAddress((void**)&p_wvh, g_wvh);
    cudaGetSymbolAddress((void**)&p_woh, g_woh);
    cudaGetSymbolAddress((void**)&p_w1h, g_w1h);
    cudaGetSymbolAddress((void**)&p_w2h, g_w2h);
    cudaGetSymbolAddress((void**)&p_atth, g_atth);

    constexpr int SH_G  = 2 * 35840;                 // 71680
    constexpr int SH_FA = 2 * 18688;                 // 37376
    cudaFuncSetAttribute((const void*)tgemm<0,768,768>,   cudaFuncAttributeMaxDynamicSharedMemorySize, SH_G);
    cudaFuncSetAttribute((const void*)tgemm<3,768,768>,   cudaFuncAttributeMaxDynamicSharedMemorySize, SH_G);
    cudaFuncSetAttribute((const void*)tgemm<4,768,3072>,  cudaFuncAttributeMaxDynamicSharedMemorySize, SH_G);
    cudaFuncSetAttribute((const void*)tgemm<5,3072,768>,  cudaFuncAttributeMaxDynamicSharedMemorySize, SH_G);
    cudaFuncSetAttribute((const void*)fattn, cudaFuncAttributeMaxDynamicSharedMemorySize, SH_FA);

    zero_small<<<1, 32>>>();

    // merged small fp32->fp16 conversions (x, Wq, Wk, Wv, Wo)
    constexpr int N4ALL = T_*D_/4 + 4*(D_*D_/4);
    f2h5<<<(N4ALL + 255)/256, 256>>>(x, p_xh, Wq, p_wqh, Wk, p_wkh, Wv, p_wvh, Wo, p_woh);

    // fused QKV projections (fp16 in, fp16 q/k/v out)
    tgemm<0,768,768><<<dim3(6,64,3), 128, SH_G>>>(p_xh, p_wqh, p_wkh, p_wvh, bq, bk, bv);

    // fused flash attention (fp16 MMA, register P, log2-domain softmax)
    fattn<<<dim3(8, 96), 256, SH_FA>>>(mask);

    // att = LN1(x + ctxh@Wo + bo) ; fp16 mirror for MoE
    tgemm<3,768,768><<<dim3(6,64,1), 128, SH_G>>>(nullptr, p_woh, nullptr, nullptr, nullptr, nullptr, nullptr);
    ln_kernel<<<T_, 256>>>(x, p_tmp, bo, ln1g, ln1b, p_att, p_atth);

    // router + MoE (fp16 operands, fp32 accum)
    router_kernel<<<T_/8, 256>>>(Wr, br);
    f2h2<<<(2*(E_*D_*FF_/4) + 255)/256, 256>>>(W1, p_w1h, W2, p_w2h, E_*D_*FF_/4);
    tgemm<4,768,3072><<<dim3(FF_/128, (E_*CAP_)/128, 1), 128, SH_G>>>(nullptr, p_w1h, nullptr, nullptr, b1, nullptr, nullptr);
    tgemm<5,3072,768><<<dim3(D_/128, (E_*CAP_)/128, 1), 128, SH_G>>>(nullptr, p_w2h, nullptr, nullptr, b2, nullptr, nullptr);

    // out = LN2(att + ffn)
    ln_kernel<<<T_, 256>>>(p_att, p_ffn, nullptr, ln2g, ln2b, out, nullptr);
}